// round 16
// baseline (speedup 1.0000x reference)
#include <cuda_runtime.h>
#include <cuda_fp16.h>
#include <math.h>
#include <stdint.h>

// ---------------------------------------------------------------------------
// Problem constants
// ---------------------------------------------------------------------------
constexpr int Hn = 8, Bn = 16, Nn = 1024, Dn = 512;
constexpr int Mn = Bn * Nn;                               // 16384
constexpr size_t XEL  = (size_t)Mn * Dn;                  // 8,388,608
constexpr size_t WEL  = (size_t)Hn * Dn * Dn;             // 2,097,152
constexpr size_t PROJ = (size_t)Hn * Mn * Dn;             // 67,108,864
constexpr size_t PEL  = (size_t)Hn * Bn * Nn * Nn;        // 134,217,728
constexpr size_t HBLK2 = (size_t)Bn * Nn * Nn;            // 16M: h-block in P
constexpr size_t NROWS = (size_t)Hn * Bn * Nn;            // 131072 score rows

// ---------------------------------------------------------------------------
// Scratch (__device__ globals — allocation-free)
// ---------------------------------------------------------------------------
__device__ __half g_xq[XEL];                       // q single fp16
__device__ __half g_xk[XEL];                       // k single fp16
__device__ __half g_xv[XEL];                       // v single fp16
__device__ __half g_wqt_hi[WEL], g_wqt_lo[WEL];    // Wq^T per head
__device__ __half g_wkt_hi[WEL], g_wkt_lo[WEL];    // Wk^T per head
__device__ __half g_wvt_hi[WEL], g_wvt_lo[WEL];    // Wv^T per head
__device__ __half g_mt[WEL];                       // Mt = Wk^T Wq (single)
__device__ __half g_wvo[WEL];                      // Wvo = Wo_h @ Wv_h (single)
__device__ __half g_wop_hi[WEL], g_wop_lo[WEL];    // permuted Wo
__device__ __half g_qp[PROJ];                      // q~ single fp16
__device__ __half g_vt2[PROJ];                     // v~ [b][o][h*1024+j]
__device__ __half g_Ps[PEL];                       // e^scores (unnormalized)
__device__ float  g_psum[NROWS * 8];               // partial rowsums per col-tile
__device__ __half g_invr[NROWS];                   // 1/rowsum, fp16
__device__ float  g_wvec[Hn * Dn];                 // Wk^T bq per head
__device__ float  g_colv[NROWS];                   // scaled col terms
__device__ float  g_bfin[Dn];                      // bo + sum_h Wo_h bv_h

// ---------------------------------------------------------------------------
// Helpers
// ---------------------------------------------------------------------------
__device__ __forceinline__ uint32_t s2u(const void* p) {
    uint32_t a;
    asm("{ .reg .u64 t; cvta.to.shared.u64 t, %1; cvt.u32.u64 %0, t; }"
        : "=r"(a) : "l"(p));
    return a;
}

__device__ __forceinline__ void cp16(uint32_t saddr, const void* gaddr) {
    asm volatile("cp.async.cg.shared.global [%0], [%1], 16;"
                 :: "r"(saddr), "l"(gaddr) : "memory");
}
__device__ __forceinline__ void cp_commit() {
    asm volatile("cp.async.commit_group;" ::: "memory");
}
template <int N>
__device__ __forceinline__ void cp_wait() {
    asm volatile("cp.async.wait_group %0;" :: "n"(N) : "memory");
}

__device__ __forceinline__ void ldsm4(uint32_t* r, uint32_t addr) {
    asm volatile("ldmatrix.sync.aligned.m8n8.x4.shared.b16 {%0,%1,%2,%3}, [%4];"
        : "=r"(r[0]), "=r"(r[1]), "=r"(r[2]), "=r"(r[3]) : "r"(addr));
}

__device__ __forceinline__ void mma16816(float* d, const uint32_t* a,
                                         uint32_t b0, uint32_t b1) {
    asm volatile(
        "mma.sync.aligned.m16n8k16.row.col.f32.f16.f16.f32 "
        "{%0,%1,%2,%3}, {%4,%5,%6,%7}, {%8,%9}, {%0,%1,%2,%3};"
        : "+f"(d[0]), "+f"(d[1]), "+f"(d[2]), "+f"(d[3])
        : "r"(a[0]), "r"(a[1]), "r"(a[2]), "r"(a[3]), "r"(b0), "r"(b1));
}

__device__ __forceinline__ void split2h(float x, uint16_t& h, uint16_t& l) {
    __half hb = __float2half_rn(x);
    __half lb = __float2half_rn(x - __half2float(hb));
    h = *reinterpret_cast<uint16_t*>(&hb);
    l = *reinterpret_cast<uint16_t*>(&lb);
}
__device__ __forceinline__ uint16_t h1(float x) {
    __half hb = __float2half_rn(x);
    return *reinterpret_cast<uint16_t*>(&hb);
}

// XOR chunk swizzle for 64B rows (4 x 16B chunks): conflict-free ldmatrix.
__device__ __forceinline__ uint32_t swz(uint32_t r, uint32_t ch) {
    return r * 64u + ((ch ^ ((r >> 1) & 3u)) << 4);
}

// ---------------------------------------------------------------------------
// fp16-split batched GEMM via mma.sync (HMMA):
// TERMS=3: C = alpha*(Ahi+Alo)@(Bhi+Blo)^T, CTA 128x128, 256 thr (warp 64x32)
// TERMS=1: C = alpha* A @ B^T,              CTA 256x128, 256 thr (warp 64x64)
// KT    : k-tiles (of 32) per pipeline chunk.
// OUTM  : 0=fp32, 1=fp16 hi/lo, 3=single fp16,
//         5=single fp16 to vt2 layout [b][col][z*1024 + (row&1023)]
//         6=exp() then single fp16 + per-CTA partial rowsums to Cf(psum)
// AHB   : 0=plain A cols; 2=A col g decomposed (g>>10)*HBLK2 + (g&1023)
// BMODB : B z-index = z & 15 (B shared across heads, z = h*16+b)
// ASCALE: scale A fragments by invr (Alo repurposed; TERMS==1, AHB==2)
// 3-stage cp.async pipeline, 1 sync/chunk.
// ---------------------------------------------------------------------------
template <int TERMS, int KT> struct Cfg {
    static constexpr int MROWS  = (TERMS == 1) ? 256 : 128;  // CTA rows
    static constexpr int A_TB   = MROWS * 64;                // A tile bytes
    static constexpr int B_TB   = 128 * 64;                  // B tile bytes
    static constexpr int NAOP   = (TERMS == 3) ? 2 : 1;      // A operands
    static constexpr int NBOP   = (TERMS == 3) ? 2 : 1;      // B operands
    static constexpr int STAGE  = KT * (NAOP * A_TB + NBOP * B_TB);
    static constexpr int SMEM   = 3 * STAGE + 512 + 2048;
    static constexpr int THREADS= 256;
    static constexpr int MAXCTA = (TERMS == 1) ? 1 : 2;
    static constexpr int WCN    = (TERMS == 1) ? 2 : 4;      // warp col groups
    static constexpr int NTN    = (TERMS == 1) ? 8 : 4;      // n8 tiles / warp
    static constexpr int CSPAN  = (TERMS == 1) ? 64 : 32;    // cols / warp
};

template <int TERMS, int KT, bool BIAS, int OUTM, int AHB, bool BMODB,
          bool ASCALE>
__global__ void __launch_bounds__(Cfg<TERMS, KT>::THREADS,
                                  Cfg<TERMS, KT>::MAXCTA) hmma_gemm(
    const __half* __restrict__ Ahi, const __half* __restrict__ Alo,
    const __half* __restrict__ Bhi, const __half* __restrict__ Blo,
    const float* __restrict__ biasg,
    float* __restrict__ Cf,
    __half* __restrict__ Chi, __half* __restrict__ Clo,
    int N, int K, int lda, int ldb,
    size_t sA, size_t sB, size_t sBias, size_t sC, float alpha)
{
    using C = Cfg<TERMS, KT>;
    constexpr int STAGE = C::STAGE;
    constexpr int MROWS = C::MROWS;
    constexpr int A_TB  = C::A_TB;
    constexpr int B_TB  = C::B_TB;
    constexpr int NAOP  = C::NAOP;
    constexpr int WCN   = C::WCN;
    constexpr int NTN   = C::NTN;
    constexpr int CSPAN = C::CSPAN;
    constexpr int NOPS  = NAOP + C::NBOP;
    extern __shared__ __align__(16) char smem[];
    const uint32_t sb = s2u(smem);
    float* sbias = reinterpret_cast<float*>(smem + 3 * STAGE);
    float (*rsred)[WCN] = reinterpret_cast<float(*)[WCN]>(smem + 3 * STAGE + 512);

    const int tid  = threadIdx.x;
    const int wid  = tid >> 5, lane = tid & 31;
    const int wr   = (TERMS == 1) ? (wid >> 1) : (wid >> 2);   // row group
    const int wc   = wid & (WCN - 1);
    const int qr   = lane >> 2, qc = lane & 3;
    const int col0 = blockIdx.x * 128, row0 = blockIdx.y * MROWS;
    const size_t z = blockIdx.z;
    const size_t zb = BMODB ? (z & 15) : z;
    const __half* invr = ASCALE ? Alo : nullptr;   // repurposed slot
    Ahi += z * sA; if (TERMS == 3) Alo += z * sA;
    Bhi += zb * sB; if (TERMS >= 2) Blo += zb * sB;

    if (BIAS && tid < 128) sbias[tid] = biasg[z * sBias + col0 + tid];

    const int nCh = K / (32 * KT);

    auto prefetch = [&](int c) {
        const int k0 = c * 32 * KT;
        const uint32_t boff = sb + (uint32_t)(c % 3) * STAGE;
        #pragma unroll
        for (int t = 0; t < NOPS; t++) {
            const bool isA = (t < NAOP);
            const __half* s;
            if (TERMS == 3) s = (t == 0) ? Ahi : (t == 1) ? Alo
                              : (t == 2) ? Bhi : Blo;
            else            s = (t == 0) ? Ahi : Bhi;
            const int rows   = isA ? MROWS : 128;
            const int tileB  = isA ? A_TB : B_TB;
            const uint32_t ob = isA ? (uint32_t)(t * KT * A_TB)
                : (uint32_t)(NAOP * KT * A_TB + (t - NAOP) * KT * B_TB);
            #pragma unroll
            for (int kt = 0; kt < KT; kt++) {
                const int kk = k0 + kt * 32;
                const uint32_t tb = boff + ob + kt * tileB;
                size_t aoff;
                if (AHB == 2) aoff = ((size_t)(kk >> 10)) * HBLK2
                                   + (size_t)(kk & 1023);
                else          aoff = (size_t)kk;
                const int nIt = rows * 4 / 256;
                #pragma unroll
                for (int i = 0; i < nIt; i++) {
                    uint32_t idx = (uint32_t)(i * 256 + tid);
                    uint32_t r = idx >> 2, ch = idx & 3;
                    const __half* g;
                    if (isA) g = s + aoff + (size_t)(row0 + r) * lda + ch * 8;
                    else     g = s + (size_t)kk + (size_t)(col0 + r) * ldb + ch * 8;
                    cp16(tb + swz(r, ch), g);
                }
            }
        }
        cp_commit();
    };

    float acc[4][NTN][4] = {};
    uint32_t sc[4][2];           // ASCALE: per-row half2 scales

    prefetch(0);
    prefetch(1);

    for (int c = 0; c < nCh; ++c) {
        if (c + 1 < nCh) cp_wait<1>(); else cp_wait<0>();
        __syncthreads();
        if (c + 2 < nCh) prefetch(c + 2);

        if (ASCALE && (c & 15) == 0) {
            const int h = (c * 32 * KT) >> 10;
            const __half* iv = invr + ((size_t)h * Bn + z) * 1024 + row0;
            #pragma unroll
            for (int mt = 0; mt < 4; mt++) {
                #pragma unroll
                for (int rr = 0; rr < 2; rr++) {
                    __half x = iv[wr * 64 + mt * 16 + rr * 8 + qr];
                    __half2 x2 = __half2half2(x);
                    sc[mt][rr] = *reinterpret_cast<uint32_t*>(&x2);
                }
            }
        }

        const uint32_t boff = sb + (uint32_t)(c % 3) * STAGE;
        const uint32_t lrow = (uint32_t)(lane & 15), lhalf = (uint32_t)(lane >> 4);

        #pragma unroll
        for (int ks = 0; ks < 2 * KT; ks++) {
            const uint32_t ktI = (uint32_t)(ks >> 1);
            const uint32_t kch = (uint32_t)(ks & 1) * 2u + lhalf;
            const uint32_t aHiB = boff + ktI * A_TB;
            const uint32_t aLoB = boff + (uint32_t)(KT * A_TB) + ktI * A_TB;
            const uint32_t bB0  = boff + (uint32_t)(NAOP * KT * A_TB);
            const uint32_t bHiB = bB0 + ktI * B_TB;
            const uint32_t bLoB = bB0 + (uint32_t)(KT * B_TB) + ktI * B_TB;

            uint32_t bh[NTN][2], bl[4][2];
            #pragma unroll
            for (int np = 0; np < NTN / 2; np++) {
                uint32_t r = (uint32_t)(wc * CSPAN + np * 16) + lrow;
                uint32_t t[4];
                ldsm4(t, bHiB + swz(r, kch));
                bh[np*2+0][0] = t[0]; bh[np*2+0][1] = t[2];
                bh[np*2+1][0] = t[1]; bh[np*2+1][1] = t[3];
                if (TERMS >= 2) {
                    ldsm4(t, bLoB + swz(r, kch));
                    bl[np*2+0][0] = t[0]; bl[np*2+0][1] = t[2];
                    bl[np*2+1][0] = t[1]; bl[np*2+1][1] = t[3];
                }
            }
            #pragma unroll
            for (int mt = 0; mt < 4; mt++) {
                uint32_t r = (uint32_t)(wr * 64 + mt * 16) + lrow;
                uint32_t ah[4], al[4];
                ldsm4(ah, aHiB + swz(r, kch));
                if (ASCALE) {
                    __half2* av = reinterpret_cast<__half2*>(ah);
                    __half2 s0 = *reinterpret_cast<__half2*>(&sc[mt][0]);
                    __half2 s1 = *reinterpret_cast<__half2*>(&sc[mt][1]);
                    av[0] = __hmul2(av[0], s0);
                    av[2] = __hmul2(av[2], s0);
                    av[1] = __hmul2(av[1], s1);
                    av[3] = __hmul2(av[3], s1);
                }
                if (TERMS == 3) ldsm4(al, aLoB + swz(r, kch));
                #pragma unroll
                for (int nt = 0; nt < NTN; nt++) {
                    mma16816(acc[mt][nt], ah, bh[nt][0], bh[nt][1]);
                    if (TERMS >= 2)
                        mma16816(acc[mt][nt], ah, bl[nt][0], bl[nt][1]);
                    if (TERMS == 3)
                        mma16816(acc[mt][nt], al, bh[nt][0], bh[nt][1]);
                }
            }
        }
    }

    // ---- epilogue ----
    float rs[4][2] = {};          // OUTM==6 partial rowsums
    #pragma unroll
    for (int mt = 0; mt < 4; mt++) {
        #pragma unroll
        for (int nt = 0; nt < NTN; nt++) {
            const int lcol = wc * CSPAN + nt * 8 + qc * 2;
            const float b0 = BIAS ? sbias[lcol]     : 0.f;
            const float b1 = BIAS ? sbias[lcol + 1] : 0.f;
            const int r0 = row0 + wr * 64 + mt * 16 + qr;
            const float v00 = alpha * acc[mt][nt][0] + b0;
            const float v01 = alpha * acc[mt][nt][1] + b1;
            const float v10 = alpha * acc[mt][nt][2] + b0;
            const float v11 = alpha * acc[mt][nt][3] + b1;
            if (OUTM == 0) {
                float* cp = Cf + z * sC + (size_t)r0 * N + col0 + lcol;
                *reinterpret_cast<float2*>(cp)            = make_float2(v00, v01);
                *reinterpret_cast<float2*>(cp + 8ull * N) = make_float2(v10, v11);
            } else if (OUTM == 1) {
                uint16_t h0,l0,h1b,l1,h2,l2,h3,l3;
                split2h(v00, h0, l0); split2h(v01, h1b, l1);
                split2h(v10, h2, l2); split2h(v11, h3, l3);
                size_t o0 = z * sC + (size_t)r0 * N + col0 + lcol;
                size_t o1 = o0 + 8ull * N;
                *reinterpret_cast<uint32_t*>(
                    reinterpret_cast<uint16_t*>(Chi) + o0) = (uint32_t)h0 | ((uint32_t)h1b << 16);
                *reinterpret_cast<uint32_t*>(
                    reinterpret_cast<uint16_t*>(Clo) + o0) = (uint32_t)l0 | ((uint32_t)l1 << 16);
                *reinterpret_cast<uint32_t*>(
                    reinterpret_cast<uint16_t*>(Chi) + o1) = (uint32_t)h2 | ((uint32_t)h3 << 16);
                *reinterpret_cast<uint32_t*>(
                    reinterpret_cast<uint16_t*>(Clo) + o1) = (uint32_t)l2 | ((uint32_t)l3 << 16);
            } else if (OUTM == 3 || OUTM == 6) {
                float e00 = v00, e01 = v01, e10 = v10, e11 = v11;
                if (OUTM == 6) {
                    e00 = __expf(v00); e01 = __expf(v01);
                    e10 = __expf(v10); e11 = __expf(v11);
                    rs[mt][0] += e00 + e01;
                    rs[mt][1] += e10 + e11;
                }
                size_t o0 = z * sC + (size_t)r0 * N + col0 + lcol;
                size_t o1 = o0 + 8ull * N;
                *reinterpret_cast<uint32_t*>(
                    reinterpret_cast<uint16_t*>(Chi) + o0) =
                    (uint32_t)h1(e00) | ((uint32_t)h1(e01) << 16);
                *reinterpret_cast<uint32_t*>(
                    reinterpret_cast<uint16_t*>(Chi) + o1) =
                    (uint32_t)h1(e10) | ((uint32_t)h1(e11) << 16);
            } else {
                // OUTM == 5: vt2[b][col][z*1024 + j],  b = r0>>10, j = r0&1023
                uint16_t* oh = reinterpret_cast<uint16_t*>(Chi);
                const size_t bb = (size_t)(r0 >> 10);
                const int j0 = r0 & 1023;
                const size_t c0a = (bb * 512 + (size_t)(col0 + lcol)) * 8192
                                 + (size_t)z * 1024;
                const size_t c1a = c0a + 8192;       // col+1
                oh[c0a + j0]     = h1(v00);
                oh[c1a + j0]     = h1(v01);
                oh[c0a + j0 + 8] = h1(v10);
                oh[c1a + j0 + 8] = h1(v11);
            }
        }
    }

    if (OUTM == 6) {
        // reduce rowsums: over qc (shfl), then over wc (smem), write psum
        #pragma unroll
        for (int mt = 0; mt < 4; mt++) {
            #pragma unroll
            for (int rr = 0; rr < 2; rr++) {
                float v = rs[mt][rr];
                v += __shfl_xor_sync(0xffffffffu, v, 1);
                v += __shfl_xor_sync(0xffffffffu, v, 2);
                if (qc == 0)
                    rsred[wr * 64 + mt * 16 + rr * 8 + qr][wc] = v;
            }
        }
        __syncthreads();
        if (tid < MROWS) {
            float t = 0.f;
            #pragma unroll
            for (int u = 0; u < WCN; u++) t += rsred[tid][u];
            Cf[((size_t)z * 1024 + row0 + tid) * 8 + blockIdx.x] = t;
        }
    }
}

// ---------------------------------------------------------------------------
// fp32 -> fp16 conversion for q,k,v in one launch (grid.z picks tensor)
// ---------------------------------------------------------------------------
__global__ void conv_h3(const float* __restrict__ s0, __half* __restrict__ d0,
                        const float* __restrict__ s1, __half* __restrict__ d1,
                        const float* __restrict__ s2, __half* __restrict__ d2) {
    const float* s = (blockIdx.z == 0) ? s0 : (blockIdx.z == 1) ? s1 : s2;
    __half*      d = (blockIdx.z == 0) ? d0 : (blockIdx.z == 1) ? d1 : d2;
    size_t i = ((size_t)blockIdx.x * 256 + threadIdx.x) * 4;
    float4 v = *reinterpret_cast<const float4*>(s + i);
    *reinterpret_cast<uint2*>(d + i) = make_uint2(
        (uint32_t)h1(v.x) | ((uint32_t)h1(v.y) << 16),
        (uint32_t)h1(v.z) | ((uint32_t)h1(v.w) << 16));
}

// ---------------------------------------------------------------------------
// Merged per-head 512x512 transpose + split for Wq,Wk,Wv (z = 0..23)
// ---------------------------------------------------------------------------
__global__ void transpose_w3(const float* __restrict__ Wq,
                             __half* __restrict__ oq_h, __half* __restrict__ oq_l,
                             const float* __restrict__ Wk,
                             __half* __restrict__ ok_h, __half* __restrict__ ok_l,
                             const float* __restrict__ Wv,
                             __half* __restrict__ ov_h, __half* __restrict__ ov_l) {
    __shared__ float t[32][33];
    const int sel = blockIdx.z >> 3;
    const size_t z = blockIdx.z & 7;
    const float* in = (sel == 0) ? Wq : (sel == 1) ? Wk : Wv;
    __half* oh = (sel == 0) ? oq_h : (sel == 1) ? ok_h : ov_h;
    __half* ol = (sel == 0) ? oq_l : (sel == 1) ? ok_l : ov_l;
    in += z * (size_t)(Dn * Dn);
    oh += z * (size_t)(Dn * Dn);
    ol += z * (size_t)(Dn * Dn);
    const int x0 = blockIdx.x * 32;
    const int y0 = blockIdx.y * 32;
    #pragma unroll
    for (int i = 0; i < 4; i++)
        t[threadIdx.y + i * 8][threadIdx.x] =
            in[(size_t)(y0 + threadIdx.y + i * 8) * Dn + x0 + threadIdx.x];
    __syncthreads();
    #pragma unroll
    for (int i = 0; i < 4; i++) {
        float v = t[threadIdx.x][threadIdx.y + i * 8];
        uint16_t h, l;
        split2h(v, h, l);
        size_t o = (size_t)(x0 + threadIdx.y + i * 8) * Dn + y0 + threadIdx.x;
        reinterpret_cast<uint16_t*>(oh)[o] = h;
        reinterpret_cast<uint16_t*>(ol)[o] = l;
    }
}

// ---------------------------------------------------------------------------
// Wo permute + split: wo_p[o][h*512+d] = Wo[o][d*8+h]
// ---------------------------------------------------------------------------
__global__ void conv_wo_p(const float* __restrict__ Wo,
                          __half* __restrict__ oh,
                          __half* __restrict__ ol) {
    size_t idx = (size_t)blockIdx.x * 256 + threadIdx.x;
    int g = (int)(idx & 4095);
    size_t o = idx >> 12;
    int f = ((g & 511) << 3) | (g >> 9);
    float v = Wo[(o << 12) + f];
    uint16_t h, l;
    split2h(v, h, l);
    reinterpret_cast<uint16_t*>(oh)[idx] = h;
    reinterpret_cast<uint16_t*>(ol)[idx] = l;
}

// ---------------------------------------------------------------------------
// bfin[o] = bo[o] + sum_f Wo[o][f] * bv[f&7][f>>3]
// ---------------------------------------------------------------------------
__global__ void bfin_kernel(const float* __restrict__ Wo,
                            const float* __restrict__ bv,
                            const float* __restrict__ bo,
                            float* __restrict__ bfin) {
    __shared__ float red[8];
    const int o = blockIdx.x, tid = threadIdx.x;
    const float* wr = Wo + (size_t)o * 4096;
    float s = 0.f;
    for (int f = tid; f < 4096; f += 256)
        s += wr[f] * bv[(f & 7) * Dn + (f >> 3)];
    #pragma unroll
    for (int off = 16; off > 0; off >>= 1)
        s += __shfl_xor_sync(0xffffffffu, s, off);
    if ((tid & 31) == 0) red[tid >> 5] = s;
    __syncthreads();
    if (tid == 0) {
        float t = 0.f;
        #pragma unroll
        for (int i = 0; i < 8; i++) t += red[i];
        bfin[o] = bo[o] + t;
    }
}

// ---------------------------------------------------------------------------
// wvec[h][d] = sum_e bq[h][e] * Wk[h][e][d]
// ---------------------------------------------------------------------------
__global__ void wvec_kernel(const float* __restrict__ Wk,
                            const float* __restrict__ bq,
                            float* __restrict__ wvec) {
    const int h = blockIdx.x, d = threadIdx.x;
    const float* wk = Wk + (size_t)h * Dn * Dn;
    const float* b  = bq + (size_t)h * Dn;
    float s = 0.f;
    for (int e = 0; e < Dn; e++) s += b[e] * wk[(size_t)e * Dn + d];
    wvec[h * Dn + d] = s;
}

// ---------------------------------------------------------------------------
// colv[(h*16+b)][j] = inv_scale * k[b][j] . wvec[h]
// ---------------------------------------------------------------------------
__global__ void colv_kernel(const float* __restrict__ k,
                            const float* __restrict__ wvec,
                            float* __restrict__ colv, float inv_scale) {
    __shared__ float kr[Dn];
    const size_t bj = blockIdx.x;
    const int tid = threadIdx.x, w = tid >> 5, lane = tid & 31;
    const float* kp = k + bj * Dn;
    #pragma unroll
    for (int i = 0; i < 2; i++) kr[tid + i * 256] = kp[tid + i * 256];
    __syncthreads();
    const float* wv = wvec + w * Dn;
    float s = 0.f;
    #pragma unroll
    for (int t = 0; t < 16; t++) {
        int d = lane + t * 32;
        s += kr[d] * wv[d];
    }
    #pragma unroll
    for (int o = 16; o > 0; o >>= 1)
        s += __shfl_xor_sync(0xffffffffu, s, o);
    if (lane == 0) {
        size_t b = bj >> 10, j = bj & 1023;
        colv[((size_t)w * 16 + b) * 1024 + j] = s * inv_scale;
    }
}

// ---------------------------------------------------------------------------
// invr[r] = fp16( 1 / sum_{t=0..7} psum[r*8+t] )
// ---------------------------------------------------------------------------
__global__ void inv_rsum(const float* __restrict__ psum,
                         __half* __restrict__ invr) {
    size_t r = (size_t)blockIdx.x * 256 + threadIdx.x;
    const float4* p = reinterpret_cast<const float4*>(psum + r * 8);
    float4 a = p[0], b = p[1];
    float s = ((a.x + a.y) + (a.z + a.w)) + ((b.x + b.y) + (b.z + b.w));
    invr[r] = __float2half_rn(1.0f / s);
}

// ---------------------------------------------------------------------------
// kernel_launch — inputs: k, v, q, Wk, bk, Wv, bv, Wq, bq, Wo, bo
// Multi-stream fork/join (graph-capture-legal).
// ---------------------------------------------------------------------------
extern "C" void kernel_launch(void* const* d_in, const int* in_sizes, int n_in,
                              void* d_out, int out_size) {
    (void)in_sizes; (void)n_in; (void)out_size;
    const float* k  = (const float*)d_in[0];
    const float* v  = (const float*)d_in[1];
    const float* q  = (const float*)d_in[2];
    const float* Wk = (const float*)d_in[3];
    const float* Wv = (const float*)d_in[5];
    const float* bv = (const float*)d_in[6];
    const float* Wq = (const float*)d_in[7];
    const float* bq = (const float*)d_in[8];
    const float* Wo = (const float*)d_in[9];
    const float* bo = (const float*)d_in[10];
    float* out = (float*)d_out;

    constexpr int SM3  = Cfg<3, 1>::SMEM;     // 100864
    constexpr int SM1B = Cfg<1, 2>::SMEM;     // 150016
    static cudaStream_t s1 = nullptr, s2 = nullptr;
    static cudaEvent_t eRoot, eT, eMt, eWvo, eC, eV, e2end;
    if (s1 == nullptr) {
        cudaStreamCreateWithFlags(&s1, cudaStreamNonBlocking);
        cudaStreamCreateWithFlags(&s2, cudaStreamNonBlocking);
        cudaEventCreateWithFlags(&eRoot, cudaEventDisableTiming);
        cudaEventCreateWithFlags(&eT,    cudaEventDisableTiming);
        cudaEventCreateWithFlags(&eMt,   cudaEventDisableTiming);
        cudaEventCreateWithFlags(&eWvo,  cudaEventDisableTiming);
        cudaEventCreateWithFlags(&eC,    cudaEventDisableTiming);
        cudaEventCreateWithFlags(&eV,    cudaEventDisableTiming);
        cudaEventCreateWithFlags(&e2end, cudaEventDisableTiming);
        cudaFuncSetAttribute(hmma_gemm<3, 1, false, 3, 0, false, false>,
            cudaFuncAttributeMaxDynamicSharedMemorySize, SM3);
        cudaFuncSetAttribute(hmma_gemm<1, 2, false, 3, 0, false, false>,
            cudaFuncAttributeMaxDynamicSharedMemorySize, SM1B);
        cudaFuncSetAttribute(hmma_gemm<1, 2, false, 5, 0, false, false>,
            cudaFuncAttributeMaxDynamicSharedMemorySize, SM1B);
        cudaFuncSetAttribute(hmma_gemm<1, 2, true, 6, 0, true, false>,
            cudaFuncAttributeMaxDynamicSharedMemorySize, SM1B);
        cudaFuncSetAttribute(hmma_gemm<1, 2, true, 0, 2, false, true>,
            cudaFuncAttributeMaxDynamicSharedMemorySize, SM1B);
    }

    __half *xq,*xk,*xv;
    __half *wqt_h,*wqt_l,*wkt_h,*wkt_l,*wvt_h,*wvt_l,*mt,*wvo;
    __half *wop_h,*wop_l;
    __half *qp,*vt2,*Ps,*invr;
    float *wvec,*colv,*bfin,*psum;
    cudaGetSymbolAddress((void**)&xq,   g_xq);
    cudaGetSymbolAddress((void**)&xk,   g_xk);
    cudaGetSymbolAddress((void**)&xv,   g_xv);
    cudaGetSymbolAddress((void**)&wqt_h,g_wqt_hi);cudaGetSymbolAddress((void**)&wqt_l,g_wqt_lo);
    cudaGetSymbolAddress((void**)&wkt_h,g_wkt_hi);cudaGetSymbolAddress((void**)&wkt_l,g_wkt_lo);
    cudaGetSymbolAddress((void**)&wvt_h,g_wvt_hi);cudaGetSymbolAddress((void**)&wvt_l,g_wvt_lo);
    cudaGetSymbolAddress((void**)&mt,   g_mt);
    cudaGetSymbolAddress((void**)&wvo,  g_wvo);
    cudaGetSymbolAddress((void**)&wop_h,g_wop_hi);cudaGetSymbolAddress((void**)&wop_l,g_wop_lo);
    cudaGetSymbolAddress((void**)&qp,   g_qp);
    cudaGetSymbolAddress((void**)&vt2,  g_vt2);
    cudaGetSymbolAddress((void**)&Ps,   g_Ps);
    cudaGetSymbolAddress((void**)&invr, g_invr);
    cudaGetSymbolAddress((void**)&wvec, g_wvec);
    cudaGetSymbolAddress((void**)&colv, g_colv);
    cudaGetSymbolAddress((void**)&bfin, g_bfin);
    cudaGetSymbolAddress((void**)&psum, g_psum);

    const float inv_scale = 1.0f / sqrtf((float)Dn);
    const size_t WW = (size_t)Dn * Dn;
    cudaStream_t s0 = 0;

    // ---- fork ----
    cudaEventRecord(eRoot, s0);
    cudaStreamWaitEvent(s1, eRoot, 0);
    cudaStreamWaitEvent(s2, eRoot, 0);

    // s0: q,k,v -> fp16
    conv_h3<<<dim3((unsigned)(XEL / 1024), 1, 3), 256, 0, s0>>>(
        q, xq, k, xk, v, xv);
    cudaEventRecord(eC, s0);

    // s1: weight transposes -> Mt
    transpose_w3<<<dim3(16, 16, 24), dim3(32, 8), 0, s1>>>(
        Wq, wqt_h, wqt_l, Wk, wkt_h, wkt_l, Wv, wvt_h, wvt_l);
    cudaEventRecord(eT, s1);
    hmma_gemm<3, 1, false, 3, 0, false, false><<<dim3(4, 4, Hn), 256, SM3, s1>>>(
        wkt_h, wkt_l, wqt_h, wqt_l, nullptr, nullptr, mt, nullptr,
        Dn, Dn, Dn, Dn, WW, WW, 0, WW, 1.0f);
    cudaEventRecord(eMt, s1);

    // s2: wvec, bfin, wo permute -> Wvo -> colv
    wvec_kernel<<<Hn, Dn, 0, s2>>>(Wk, bq, wvec);
    bfin_kernel<<<Dn, 256, 0, s2>>>(Wo, bv, bo, bfin);
    conv_wo_p<<<(unsigned)(WEL / 256), 256, 0, s2>>>(Wo, wop_h, wop_l);
    cudaStreamWaitEvent(s2, eT, 0);
    hmma_gemm<3, 1, false, 3, 0, false, false><<<dim3(4, 4, Hn), 256, SM3, s2>>>(
        wop_h, wop_l, wvt_h, wvt_l, nullptr, nullptr, wvo, nullptr,
        Dn, Dn, Hn * Dn, Dn, (size_t)Dn, WW, 0, WW, 1.0f);
    cudaEventRecord(eWvo, s2);
    colv_kernel<<<Mn, 256, 0, s2>>>(k, wvec, colv, inv_scale);
    cudaEventRecord(e2end, s2);

    // s0: q~ = q @ Mt^T  (waits Mt)   256-row tiles
    dim3 gproj(Dn / 128, Mn / 256, Hn);
    cudaStreamWaitEvent(s0, eMt, 0);
    hmma_gemm<1, 2, false, 3, 0, false, false><<<gproj, 256, SM1B, s0>>>(
        xq, nullptr, mt, nullptr, nullptr, nullptr, qp, nullptr,
        Dn, Dn, Dn, Dn, 0, WW, 0, (size_t)Mn * Dn, 1.0f);

    // s1: v~ = v @ Wvo^T  (waits Wvo + conv_h3)
    cudaStreamWaitEvent(s1, eWvo, 0);
    cudaStreamWaitEvent(s1, eC, 0);
    hmma_gemm<1, 2, false, 5, 0, false, false><<<gproj, 256, SM1B, s1>>>(
        xv, nullptr, wvo, nullptr, nullptr, nullptr, vt2, nullptr,
        Dn, Dn, Dn, Dn, 0, WW, 0, 0, 1.0f);
    cudaEventRecord(eV, s1);

    // s0: scores (waits s2 join for colv)
    cudaStreamWaitEvent(s0, e2end, 0);
    dim3 gsc(Nn / 128, Nn / 256, Hn * Bn);
    hmma_gemm<1, 2, true, 6, 0, true, false><<<gsc, 256, SM1B, s0>>>(
        qp, nullptr, xk, nullptr, colv, psum, Ps, nullptr,
        Nn, Dn, Dn, Dn, (size_t)Nn * Dn, (size_t)Nn * Dn,
        (size_t)Nn, (size_t)Nn * Nn, inv_scale);

    // s0: invr = 1 / rowsum
    inv_rsum<<<(unsigned)(NROWS / 256), 256, 0, s0>>>(psum, invr);

    // s0: final (waits v~)
    cudaStreamWaitEvent(s0, eV, 0);
    dim3 gfin(Dn / 128, Nn / 256, Bn);
    hmma_gemm<1, 2, true, 0, 2, false, true><<<gfin, 256, SM1B, s0>>>(
        Ps, invr /*repurposed*/, vt2, nullptr, bfin, out, nullptr, nullptr,
        Dn, Hn * Nn, Nn, Hn * Nn,
        (size_t)Nn * Nn, (size_t)Dn * Hn * Nn, 0, (size_t)Nn * Dn, 1.0f);
}

// round 17
// speedup vs baseline: 1.0603x; 1.0603x over previous
#include <cuda_runtime.h>
#include <cuda_fp16.h>
#include <math.h>
#include <stdint.h>

// ---------------------------------------------------------------------------
// Problem constants
// ---------------------------------------------------------------------------
constexpr int Hn = 8, Bn = 16, Nn = 1024, Dn = 512;
constexpr int Mn = Bn * Nn;                               // 16384
constexpr size_t XEL  = (size_t)Mn * Dn;                  // 8,388,608
constexpr size_t WEL  = (size_t)Hn * Dn * Dn;             // 2,097,152
constexpr size_t PROJ = (size_t)Hn * Mn * Dn;             // 67,108,864
constexpr size_t PEL  = (size_t)Hn * Bn * Nn * Nn;        // 134,217,728
constexpr size_t HBLK2 = (size_t)Bn * Nn * Nn;            // 16M: h-block in P
constexpr size_t NROWS = (size_t)Hn * Bn * Nn;            // 131072 score rows

// ---------------------------------------------------------------------------
// Scratch (__device__ globals — allocation-free)
// ---------------------------------------------------------------------------
__device__ __half g_xq[XEL];                       // q single fp16
__device__ __half g_xk[XEL];                       // k single fp16
__device__ __half g_xv[XEL];                       // v single fp16
__device__ __half g_wqt_hi[WEL], g_wqt_lo[WEL];    // Wq^T per head
__device__ __half g_wkt_hi[WEL], g_wkt_lo[WEL];    // Wk^T per head
__device__ __half g_wvt_hi[WEL], g_wvt_lo[WEL];    // Wv^T per head
__device__ __half g_mt[WEL];                       // Mt = Wk^T Wq (single)
__device__ __half g_wvo[WEL];                      // Wvo = Wo_h @ Wv_h (single)
__device__ __half g_wop_hi[WEL], g_wop_lo[WEL];    // permuted Wo
__device__ __half g_qp[PROJ];                      // q~ single fp16
__device__ __half g_vt2[PROJ];                     // v~ [b][o][h*1024+j]
__device__ __half g_Ps[PEL];                       // e^scores (unnormalized)
__device__ float  g_psum[NROWS * 8];               // partial rowsums per col-tile
__device__ __half g_invr[NROWS];                   // 1/rowsum, fp16
__device__ float  g_wvec[Hn * Dn];                 // Wk^T bq per head
__device__ float  g_colv[NROWS];                   // scaled col terms
__device__ float  g_bfin[Dn];                      // bo + sum_h Wo_h bv_h

// ---------------------------------------------------------------------------
// Helpers
// ---------------------------------------------------------------------------
__device__ __forceinline__ uint32_t s2u(const void* p) {
    uint32_t a;
    asm("{ .reg .u64 t; cvta.to.shared.u64 t, %1; cvt.u32.u64 %0, t; }"
        : "=r"(a) : "l"(p));
    return a;
}

__device__ __forceinline__ void cp16(uint32_t saddr, const void* gaddr) {
    asm volatile("cp.async.cg.shared.global [%0], [%1], 16;"
                 :: "r"(saddr), "l"(gaddr) : "memory");
}
__device__ __forceinline__ void cp_commit() {
    asm volatile("cp.async.commit_group;" ::: "memory");
}
template <int N>
__device__ __forceinline__ void cp_wait() {
    asm volatile("cp.async.wait_group %0;" :: "n"(N) : "memory");
}

__device__ __forceinline__ void ldsm4(uint32_t* r, uint32_t addr) {
    asm volatile("ldmatrix.sync.aligned.m8n8.x4.shared.b16 {%0,%1,%2,%3}, [%4];"
        : "=r"(r[0]), "=r"(r[1]), "=r"(r[2]), "=r"(r[3]) : "r"(addr));
}

__device__ __forceinline__ void mma16816(float* d, const uint32_t* a,
                                         uint32_t b0, uint32_t b1) {
    asm volatile(
        "mma.sync.aligned.m16n8k16.row.col.f32.f16.f16.f32 "
        "{%0,%1,%2,%3}, {%4,%5,%6,%7}, {%8,%9}, {%0,%1,%2,%3};"
        : "+f"(d[0]), "+f"(d[1]), "+f"(d[2]), "+f"(d[3])
        : "r"(a[0]), "r"(a[1]), "r"(a[2]), "r"(a[3]), "r"(b0), "r"(b1));
}

__device__ __forceinline__ void split2h(float x, uint16_t& h, uint16_t& l) {
    __half hb = __float2half_rn(x);
    __half lb = __float2half_rn(x - __half2float(hb));
    h = *reinterpret_cast<uint16_t*>(&hb);
    l = *reinterpret_cast<uint16_t*>(&lb);
}
__device__ __forceinline__ uint16_t h1(float x) {
    __half hb = __float2half_rn(x);
    return *reinterpret_cast<uint16_t*>(&hb);
}

// XOR chunk swizzle for 64B rows (4 x 16B chunks): conflict-free ldmatrix.
__device__ __forceinline__ uint32_t swz(uint32_t r, uint32_t ch) {
    return r * 64u + ((ch ^ ((r >> 1) & 3u)) << 4);
}

// ---------------------------------------------------------------------------
// fp16-split batched GEMM via mma.sync (HMMA):
// TERMS=3:  C = alpha*(Ahi+Alo)@(Bhi+Blo)^T   (256 thr, warp 64x32)
// TERMS=1:  C = alpha* A @ B^T (both single)  (128 thr, warp 64x64)
// KT    : k-tiles (of 32) per pipeline chunk.
// OUTM  : 0=fp32, 1=fp16 hi/lo, 3=single fp16,
//         5=single fp16 to vt2 layout [b][col][z*1024 + (row&1023)]
//         6=exp() then single fp16 + per-CTA partial rowsums to Cf(psum)
// AHB   : 0=plain A cols; 2=A col g decomposed (g>>10)*HBLK2 + (g&1023)
// BMODB : B z-index = z & 15 (B shared across heads, z = h*16+b)
// ASCALE: scale A fragments by invr (Alo repurposed; TERMS==1, AHB==2)
// ZSPL  : 0 -> z = blockIdx.z
//         1 -> z = (bz>>3)*16 + zoff + (bz&7)   (scores b-half split)
//         2 -> z = bz + zoff                    (final b-half split)
// CTA tile 128x128, 3-stage cp.async pipeline, 1 sync/chunk. 2 CTAs/SM.
// ---------------------------------------------------------------------------
constexpr int TILE_B = 128 * 64;                 // 8192 B per 32-k tile

template <int TERMS, int KT> struct Cfg {
    static constexpr int NOPS    = (TERMS == 3) ? 4 : (TERMS == 2) ? 3 : 2;
    static constexpr int STAGE   = NOPS * KT * TILE_B;
    static constexpr int SMEM    = 3 * STAGE + 512 + 2048;
    static constexpr int THREADS = (TERMS == 1) ? 128 : 256;
    static constexpr int WCN     = (TERMS == 1) ? 2 : 4;   // warp col groups
    static constexpr int NTN     = (TERMS == 1) ? 8 : 4;   // n8 tiles / warp
    static constexpr int CSPAN   = (TERMS == 1) ? 64 : 32; // cols / warp
};

template <int TERMS, int KT, bool BIAS, int OUTM, int AHB, bool BMODB,
          bool ASCALE, int ZSPL>
__global__ void __launch_bounds__(Cfg<TERMS, KT>::THREADS, 2) hmma_gemm(
    const __half* __restrict__ Ahi, const __half* __restrict__ Alo,
    const __half* __restrict__ Bhi, const __half* __restrict__ Blo,
    const float* __restrict__ biasg,
    float* __restrict__ Cf,
    __half* __restrict__ Chi, __half* __restrict__ Clo,
    int N, int K, int lda, int ldb,
    size_t sA, size_t sB, size_t sBias, size_t sC, float alpha, int zoff)
{
    constexpr int STAGE   = Cfg<TERMS, KT>::STAGE;
    constexpr int NOPS    = Cfg<TERMS, KT>::NOPS;
    constexpr int NA      = (TERMS == 3) ? 2 : 1;
    constexpr int THREADS = Cfg<TERMS, KT>::THREADS;
    constexpr int WCN     = Cfg<TERMS, KT>::WCN;
    constexpr int NTN     = Cfg<TERMS, KT>::NTN;
    constexpr int CSPAN   = Cfg<TERMS, KT>::CSPAN;
    extern __shared__ __align__(16) char smem[];
    const uint32_t sb = s2u(smem);
    float* sbias = reinterpret_cast<float*>(smem + 3 * STAGE);
    float (*rsred)[WCN] = reinterpret_cast<float(*)[WCN]>(smem + 3 * STAGE + 512);

    const int tid  = threadIdx.x;
    const int wid  = tid >> 5, lane = tid & 31;
    const int wr   = (TERMS == 1) ? (wid >> 1) : (wid >> 2);
    const int wc   = wid & (WCN - 1);
    const int qr   = lane >> 2, qc = lane & 3;
    const int col0 = blockIdx.x * 128, row0 = blockIdx.y * 128;
    const int bz   = (int)blockIdx.z;
    size_t z;
    if (ZSPL == 1)      z = (size_t)((bz >> 3) * 16 + zoff + (bz & 7));
    else if (ZSPL == 2) z = (size_t)(bz + zoff);
    else                z = (size_t)bz;
    const size_t zb = BMODB ? (z & 15) : z;
    const __half* invr = ASCALE ? Alo : nullptr;   // repurposed slot
    Ahi += z * sA; if (TERMS == 3) Alo += z * sA;
    Bhi += zb * sB; if (TERMS >= 2) Blo += zb * sB;

    if (BIAS && tid < 128) sbias[tid] = biasg[z * sBias + col0 + tid];

    const int nCh = K / (32 * KT);

    auto prefetch = [&](int c) {
        const int k0 = c * 32 * KT;
        const uint32_t boff = sb + (uint32_t)(c % 3) * STAGE;
        #pragma unroll
        for (int t = 0; t < NOPS; t++) {
            const __half* s;
            if (TERMS == 3) s = (t == 0) ? Ahi : (t == 1) ? Alo
                              : (t == 2) ? Bhi : Blo;
            else            s = (t == 0) ? Ahi : Bhi;
            #pragma unroll
            for (int kt = 0; kt < KT; kt++) {
                const int kk = k0 + kt * 32;
                const uint32_t tb = boff + (t * KT + kt) * TILE_B;
                size_t aoff;
                if (AHB == 2) aoff = ((size_t)(kk >> 10)) * HBLK2
                                   + (size_t)(kk & 1023);
                else          aoff = (size_t)kk;
                #pragma unroll
                for (int i = 0; i < 512 / THREADS; i++) {
                    uint32_t idx = (uint32_t)(i * THREADS + tid);   // 0..511
                    uint32_t r = idx >> 2, ch = idx & 3;
                    const __half* g;
                    if (t < NA) g = s + aoff + (size_t)(row0 + r) * lda + ch * 8;
                    else        g = s + (size_t)kk + (size_t)(col0 + r) * ldb + ch * 8;
                    cp16(tb + swz(r, ch), g);
                }
            }
        }
        cp_commit();
    };

    float acc[4][NTN][4] = {};
    uint32_t sc[4][2];           // ASCALE: per-row half2 scales

    prefetch(0);
    prefetch(1);

    for (int c = 0; c < nCh; ++c) {
        if (c + 1 < nCh) cp_wait<1>(); else cp_wait<0>();
        __syncthreads();
        if (c + 2 < nCh) prefetch(c + 2);

        if (ASCALE && (c & 15) == 0) {
            const int h = (c * 32 * KT) >> 10;
            const __half* iv = invr + ((size_t)h * Bn + z) * 1024 + row0;
            #pragma unroll
            for (int mt = 0; mt < 4; mt++) {
                #pragma unroll
                for (int rr = 0; rr < 2; rr++) {
                    __half x = iv[wr * 64 + mt * 16 + rr * 8 + qr];
                    __half2 x2 = __half2half2(x);
                    sc[mt][rr] = *reinterpret_cast<uint32_t*>(&x2);
                }
            }
        }

        const uint32_t boff = sb + (uint32_t)(c % 3) * STAGE;
        const uint32_t lrow = (uint32_t)(lane & 15), lhalf = (uint32_t)(lane >> 4);

        #pragma unroll
        for (int ks = 0; ks < 2 * KT; ks++) {
            const uint32_t sub = (uint32_t)(ks >> 1) * TILE_B;
            const uint32_t kch = (uint32_t)(ks & 1) * 2u + lhalf;
            const uint32_t aHiB = boff + sub;
            const uint32_t aLoB = boff + KT * TILE_B + sub;          // T3 only
            const uint32_t bHiB = boff + ((TERMS == 3) ? 2 : 1) * KT * TILE_B + sub;
            const uint32_t bLoB = boff + ((TERMS == 3) ? 3 : 2) * KT * TILE_B + sub;

            uint32_t bh[NTN][2], bl[4][2];
            #pragma unroll
            for (int np = 0; np < NTN / 2; np++) {
                uint32_t r = (uint32_t)(wc * CSPAN + np * 16) + lrow;
                uint32_t t[4];
                ldsm4(t, bHiB + swz(r, kch));
                bh[np*2+0][0] = t[0]; bh[np*2+0][1] = t[2];
                bh[np*2+1][0] = t[1]; bh[np*2+1][1] = t[3];
                if (TERMS >= 2) {
                    ldsm4(t, bLoB + swz(r, kch));
                    bl[np*2+0][0] = t[0]; bl[np*2+0][1] = t[2];
                    bl[np*2+1][0] = t[1]; bl[np*2+1][1] = t[3];
                }
            }
            #pragma unroll
            for (int mt = 0; mt < 4; mt++) {
                uint32_t r = (uint32_t)(wr * 64 + mt * 16) + lrow;
                uint32_t ah[4], al[4];
                ldsm4(ah, aHiB + swz(r, kch));
                if (ASCALE) {
                    __half2* av = reinterpret_cast<__half2*>(ah);
                    __half2 s0 = *reinterpret_cast<__half2*>(&sc[mt][0]);
                    __half2 s1 = *reinterpret_cast<__half2*>(&sc[mt][1]);
                    av[0] = __hmul2(av[0], s0);
                    av[2] = __hmul2(av[2], s0);
                    av[1] = __hmul2(av[1], s1);
                    av[3] = __hmul2(av[3], s1);
                }
                if (TERMS == 3) ldsm4(al, aLoB + swz(r, kch));
                #pragma unroll
                for (int nt = 0; nt < NTN; nt++) {
                    mma16816(acc[mt][nt], ah, bh[nt][0], bh[nt][1]);
                    if (TERMS >= 2)
                        mma16816(acc[mt][nt], ah, bl[nt][0], bl[nt][1]);
                    if (TERMS == 3)
                        mma16816(acc[mt][nt], al, bh[nt][0], bh[nt][1]);
                }
            }
        }
    }

    // ---- epilogue ----
    float rs[4][2] = {};          // OUTM==6 partial rowsums
    #pragma unroll
    for (int mt = 0; mt < 4; mt++) {
        #pragma unroll
        for (int nt = 0; nt < NTN; nt++) {
            const int lcol = wc * CSPAN + nt * 8 + qc * 2;
            const float b0 = BIAS ? sbias[lcol]     : 0.f;
            const float b1 = BIAS ? sbias[lcol + 1] : 0.f;
            const int r0 = row0 + wr * 64 + mt * 16 + qr;
            const float v00 = alpha * acc[mt][nt][0] + b0;
            const float v01 = alpha * acc[mt][nt][1] + b1;
            const float v10 = alpha * acc[mt][nt][2] + b0;
            const float v11 = alpha * acc[mt][nt][3] + b1;
            if (OUTM == 0) {
                float* cp = Cf + z * sC + (size_t)r0 * N + col0 + lcol;
                *reinterpret_cast<float2*>(cp)            = make_float2(v00, v01);
                *reinterpret_cast<float2*>(cp + 8ull * N) = make_float2(v10, v11);
            } else if (OUTM == 1) {
                uint16_t h0,l0,h1b,l1,h2,l2,h3,l3;
                split2h(v00, h0, l0); split2h(v01, h1b, l1);
                split2h(v10, h2, l2); split2h(v11, h3, l3);
                size_t o0 = z * sC + (size_t)r0 * N + col0 + lcol;
                size_t o1 = o0 + 8ull * N;
                *reinterpret_cast<uint32_t*>(
                    reinterpret_cast<uint16_t*>(Chi) + o0) = (uint32_t)h0 | ((uint32_t)h1b << 16);
                *reinterpret_cast<uint32_t*>(
                    reinterpret_cast<uint16_t*>(Clo) + o0) = (uint32_t)l0 | ((uint32_t)l1 << 16);
                *reinterpret_cast<uint32_t*>(
                    reinterpret_cast<uint16_t*>(Chi) + o1) = (uint32_t)h2 | ((uint32_t)h3 << 16);
                *reinterpret_cast<uint32_t*>(
                    reinterpret_cast<uint16_t*>(Clo) + o1) = (uint32_t)l2 | ((uint32_t)l3 << 16);
            } else if (OUTM == 3 || OUTM == 6) {
                float e00 = v00, e01 = v01, e10 = v10, e11 = v11;
                if (OUTM == 6) {
                    e00 = __expf(v00); e01 = __expf(v01);
                    e10 = __expf(v10); e11 = __expf(v11);
                    rs[mt][0] += e00 + e01;
                    rs[mt][1] += e10 + e11;
                }
                size_t o0 = z * sC + (size_t)r0 * N + col0 + lcol;
                size_t o1 = o0 + 8ull * N;
                *reinterpret_cast<uint32_t*>(
                    reinterpret_cast<uint16_t*>(Chi) + o0) =
                    (uint32_t)h1(e00) | ((uint32_t)h1(e01) << 16);
                *reinterpret_cast<uint32_t*>(
                    reinterpret_cast<uint16_t*>(Chi) + o1) =
                    (uint32_t)h1(e10) | ((uint32_t)h1(e11) << 16);
            } else {
                // OUTM == 5: vt2[b][col][z*1024 + j],  b = r0>>10, j = r0&1023
                uint16_t* oh = reinterpret_cast<uint16_t*>(Chi);
                const size_t bb = (size_t)(r0 >> 10);
                const int j0 = r0 & 1023;
                const size_t c0a = (bb * 512 + (size_t)(col0 + lcol)) * 8192
                                 + (size_t)z * 1024;
                const size_t c1a = c0a + 8192;       // col+1
                oh[c0a + j0]     = h1(v00);
                oh[c1a + j0]     = h1(v01);
                oh[c0a + j0 + 8] = h1(v10);
                oh[c1a + j0 + 8] = h1(v11);
            }
        }
    }

    if (OUTM == 6) {
        // reduce rowsums: over qc (shfl), then over wc (smem), write psum
        #pragma unroll
        for (int mt = 0; mt < 4; mt++) {
            #pragma unroll
            for (int rr = 0; rr < 2; rr++) {
                float v = rs[mt][rr];
                v += __shfl_xor_sync(0xffffffffu, v, 1);
                v += __shfl_xor_sync(0xffffffffu, v, 2);
                if (qc == 0)
                    rsred[wr * 64 + mt * 16 + rr * 8 + qr][wc] = v;
            }
        }
        __syncthreads();
        if (tid < 128) {
            float t = 0.f;
            #pragma unroll
            for (int u = 0; u < WCN; u++) t += rsred[tid][u];
            Cf[((size_t)z * 1024 + row0 + tid) * 8 + blockIdx.x] = t;
        }
    }
}

// ---------------------------------------------------------------------------
// fp32 -> fp16 conversion for q,k,v in one launch (grid.z picks tensor)
// ---------------------------------------------------------------------------
__global__ void conv_h3(const float* __restrict__ s0, __half* __restrict__ d0,
                        const float* __restrict__ s1, __half* __restrict__ d1,
                        const float* __restrict__ s2, __half* __restrict__ d2) {
    const float* s = (blockIdx.z == 0) ? s0 : (blockIdx.z == 1) ? s1 : s2;
    __half*      d = (blockIdx.z == 0) ? d0 : (blockIdx.z == 1) ? d1 : d2;
    size_t i = ((size_t)blockIdx.x * 256 + threadIdx.x) * 4;
    float4 v = *reinterpret_cast<const float4*>(s + i);
    *reinterpret_cast<uint2*>(d + i) = make_uint2(
        (uint32_t)h1(v.x) | ((uint32_t)h1(v.y) << 16),
        (uint32_t)h1(v.z) | ((uint32_t)h1(v.w) << 16));
}

// ---------------------------------------------------------------------------
// Merged per-head 512x512 transpose + split for Wq,Wk,Wv (z = 0..23)
// ---------------------------------------------------------------------------
__global__ void transpose_w3(const float* __restrict__ Wq,
                             __half* __restrict__ oq_h, __half* __restrict__ oq_l,
                             const float* __restrict__ Wk,
                             __half* __restrict__ ok_h, __half* __restrict__ ok_l,
                             const float* __restrict__ Wv,
                             __half* __restrict__ ov_h, __half* __restrict__ ov_l) {
    __shared__ float t[32][33];
    const int sel = blockIdx.z >> 3;
    const size_t z = blockIdx.z & 7;
    const float* in = (sel == 0) ? Wq : (sel == 1) ? Wk : Wv;
    __half* oh = (sel == 0) ? oq_h : (sel == 1) ? ok_h : ov_h;
    __half* ol = (sel == 0) ? oq_l : (sel == 1) ? ok_l : ov_l;
    in += z * (size_t)(Dn * Dn);
    oh += z * (size_t)(Dn * Dn);
    ol += z * (size_t)(Dn * Dn);
    const int x0 = blockIdx.x * 32;
    const int y0 = blockIdx.y * 32;
    #pragma unroll
    for (int i = 0; i < 4; i++)
        t[threadIdx.y + i * 8][threadIdx.x] =
            in[(size_t)(y0 + threadIdx.y + i * 8) * Dn + x0 + threadIdx.x];
    __syncthreads();
    #pragma unroll
    for (int i = 0; i < 4; i++) {
        float v = t[threadIdx.x][threadIdx.y + i * 8];
        uint16_t h, l;
        split2h(v, h, l);
        size_t o = (size_t)(x0 + threadIdx.y + i * 8) * Dn + y0 + threadIdx.x;
        reinterpret_cast<uint16_t*>(oh)[o] = h;
        reinterpret_cast<uint16_t*>(ol)[o] = l;
    }
}

// ---------------------------------------------------------------------------
// Wo permute + split: wo_p[o][h*512+d] = Wo[o][d*8+h]
// ---------------------------------------------------------------------------
__global__ void conv_wo_p(const float* __restrict__ Wo,
                          __half* __restrict__ oh,
                          __half* __restrict__ ol) {
    size_t idx = (size_t)blockIdx.x * 256 + threadIdx.x;
    int g = (int)(idx & 4095);
    size_t o = idx >> 12;
    int f = ((g & 511) << 3) | (g >> 9);
    float v = Wo[(o << 12) + f];
    uint16_t h, l;
    split2h(v, h, l);
    reinterpret_cast<uint16_t*>(oh)[idx] = h;
    reinterpret_cast<uint16_t*>(ol)[idx] = l;
}

// ---------------------------------------------------------------------------
// bfin[o] = bo[o] + sum_f Wo[o][f] * bv[f&7][f>>3]
// ---------------------------------------------------------------------------
__global__ void bfin_kernel(const float* __restrict__ Wo,
                            const float* __restrict__ bv,
                            const float* __restrict__ bo,
                            float* __restrict__ bfin) {
    __shared__ float red[8];
    const int o = blockIdx.x, tid = threadIdx.x;
    const float* wr = Wo + (size_t)o * 4096;
    float s = 0.f;
    for (int f = tid; f < 4096; f += 256)
        s += wr[f] * bv[(f & 7) * Dn + (f >> 3)];
    #pragma unroll
    for (int off = 16; off > 0; off >>= 1)
        s += __shfl_xor_sync(0xffffffffu, s, off);
    if ((tid & 31) == 0) red[tid >> 5] = s;
    __syncthreads();
    if (tid == 0) {
        float t = 0.f;
        #pragma unroll
        for (int i = 0; i < 8; i++) t += red[i];
        bfin[o] = bo[o] + t;
    }
}

// ---------------------------------------------------------------------------
// wvec[h][d] = sum_e bq[h][e] * Wk[h][e][d]
// ---------------------------------------------------------------------------
__global__ void wvec_kernel(const float* __restrict__ Wk,
                            const float* __restrict__ bq,
                            float* __restrict__ wvec) {
    const int h = blockIdx.x, d = threadIdx.x;
    const float* wk = Wk + (size_t)h * Dn * Dn;
    const float* b  = bq + (size_t)h * Dn;
    float s = 0.f;
    for (int e = 0; e < Dn; e++) s += b[e] * wk[(size_t)e * Dn + d];
    wvec[h * Dn + d] = s;
}

// ---------------------------------------------------------------------------
// colv[(h*16+b)][j] = inv_scale * k[b][j] . wvec[h]
// ---------------------------------------------------------------------------
__global__ void colv_kernel(const float* __restrict__ k,
                            const float* __restrict__ wvec,
                            float* __restrict__ colv, float inv_scale) {
    __shared__ float kr[Dn];
    const size_t bj = blockIdx.x;
    const int tid = threadIdx.x, w = tid >> 5, lane = tid & 31;
    const float* kp = k + bj * Dn;
    #pragma unroll
    for (int i = 0; i < 2; i++) kr[tid + i * 256] = kp[tid + i * 256];
    __syncthreads();
    const float* wv = wvec + w * Dn;
    float s = 0.f;
    #pragma unroll
    for (int t = 0; t < 16; t++) {
        int d = lane + t * 32;
        s += kr[d] * wv[d];
    }
    #pragma unroll
    for (int o = 16; o > 0; o >>= 1)
        s += __shfl_xor_sync(0xffffffffu, s, o);
    if (lane == 0) {
        size_t b = bj >> 10, j = bj & 1023;
        colv[((size_t)w * 16 + b) * 1024 + j] = s * inv_scale;
    }
}

// ---------------------------------------------------------------------------
// invr for b-half: rows z = h*16 + boff + bb  (h=idx>>13, bb=(idx>>10)&7)
// ---------------------------------------------------------------------------
__global__ void inv_rsum_h8(const float* __restrict__ psum,
                            __half* __restrict__ invr, int boff) {
    size_t idx = (size_t)blockIdx.x * 256 + threadIdx.x;   // 0..65535
    size_t h = idx >> 13, bb = (idx >> 10) & 7, row = idx & 1023;
    size_t r = (h * 16 + (size_t)boff + bb) * 1024 + row;
    const float4* p = reinterpret_cast<const float4*>(psum + r * 8);
    float4 a = p[0], b = p[1];
    float s = ((a.x + a.y) + (a.z + a.w)) + ((b.x + b.y) + (b.z + b.w));
    invr[r] = __float2half_rn(1.0f / s);
}

// ---------------------------------------------------------------------------
// kernel_launch — inputs: k, v, q, Wk, bk, Wv, bv, Wq, bq, Wo, bo
// Multi-stream fork/join + b-split scores/final pipelining.
// ---------------------------------------------------------------------------
extern "C" void kernel_launch(void* const* d_in, const int* in_sizes, int n_in,
                              void* d_out, int out_size) {
    (void)in_sizes; (void)n_in; (void)out_size;
    const float* k  = (const float*)d_in[0];
    const float* v  = (const float*)d_in[1];
    const float* q  = (const float*)d_in[2];
    const float* Wk = (const float*)d_in[3];
    const float* Wv = (const float*)d_in[5];
    const float* bv = (const float*)d_in[6];
    const float* Wq = (const float*)d_in[7];
    const float* bq = (const float*)d_in[8];
    const float* Wo = (const float*)d_in[9];
    const float* bo = (const float*)d_in[10];
    float* out = (float*)d_out;

    constexpr int SM3  = Cfg<3, 1>::SMEM;
    constexpr int SM1B = Cfg<1, 2>::SMEM;
    static cudaStream_t s1 = nullptr, s2 = nullptr;
    static cudaEvent_t eRoot, eT, eMt, eWvo, eC, eV, e2end, eS1, eI2;
    if (s1 == nullptr) {
        cudaStreamCreateWithFlags(&s1, cudaStreamNonBlocking);
        cudaStreamCreateWithFlags(&s2, cudaStreamNonBlocking);
        cudaEventCreateWithFlags(&eRoot, cudaEventDisableTiming);
        cudaEventCreateWithFlags(&eT,    cudaEventDisableTiming);
        cudaEventCreateWithFlags(&eMt,   cudaEventDisableTiming);
        cudaEventCreateWithFlags(&eWvo,  cudaEventDisableTiming);
        cudaEventCreateWithFlags(&eC,    cudaEventDisableTiming);
        cudaEventCreateWithFlags(&eV,    cudaEventDisableTiming);
        cudaEventCreateWithFlags(&e2end, cudaEventDisableTiming);
        cudaEventCreateWithFlags(&eS1,   cudaEventDisableTiming);
        cudaEventCreateWithFlags(&eI2,   cudaEventDisableTiming);
        cudaFuncSetAttribute(hmma_gemm<3, 1, false, 3, 0, false, false, 0>,
            cudaFuncAttributeMaxDynamicSharedMemorySize, SM3);
        cudaFuncSetAttribute(hmma_gemm<1, 2, false, 3, 0, false, false, 0>,
            cudaFuncAttributeMaxDynamicSharedMemorySize, SM1B);
        cudaFuncSetAttribute(hmma_gemm<1, 2, false, 5, 0, false, false, 0>,
            cudaFuncAttributeMaxDynamicSharedMemorySize, SM1B);
        cudaFuncSetAttribute(hmma_gemm<1, 2, true, 6, 0, true, false, 1>,
            cudaFuncAttributeMaxDynamicSharedMemorySize, SM1B);
        cudaFuncSetAttribute(hmma_gemm<1, 2, true, 0, 2, false, true, 2>,
            cudaFuncAttributeMaxDynamicSharedMemorySize, SM1B);
    }

    __half *xq,*xk,*xv;
    __half *wqt_h,*wqt_l,*wkt_h,*wkt_l,*wvt_h,*wvt_l,*mt,*wvo;
    __half *wop_h,*wop_l;
    __half *qp,*vt2,*Ps,*invr;
    float *wvec,*colv,*bfin,*psum;
    cudaGetSymbolAddress((void**)&xq,   g_xq);
    cudaGetSymbolAddress((void**)&xk,   g_xk);
    cudaGetSymbolAddress((void**)&xv,   g_xv);
    cudaGetSymbolAddress((void**)&wqt_h,g_wqt_hi);cudaGetSymbolAddress((void**)&wqt_l,g_wqt_lo);
    cudaGetSymbolAddress((void**)&wkt_h,g_wkt_hi);cudaGetSymbolAddress((void**)&wkt_l,g_wkt_lo);
    cudaGetSymbolAddress((void**)&wvt_h,g_wvt_hi);cudaGetSymbolAddress((void**)&wvt_l,g_wvt_lo);
    cudaGetSymbolAddress((void**)&mt,   g_mt);
    cudaGetSymbolAddress((void**)&wvo,  g_wvo);
    cudaGetSymbolAddress((void**)&wop_h,g_wop_hi);cudaGetSymbolAddress((void**)&wop_l,g_wop_lo);
    cudaGetSymbolAddress((void**)&qp,   g_qp);
    cudaGetSymbolAddress((void**)&vt2,  g_vt2);
    cudaGetSymbolAddress((void**)&Ps,   g_Ps);
    cudaGetSymbolAddress((void**)&invr, g_invr);
    cudaGetSymbolAddress((void**)&wvec, g_wvec);
    cudaGetSymbolAddress((void**)&colv, g_colv);
    cudaGetSymbolAddress((void**)&bfin, g_bfin);
    cudaGetSymbolAddress((void**)&psum, g_psum);

    const float inv_scale = 1.0f / sqrtf((float)Dn);
    const size_t WW = (size_t)Dn * Dn;
    cudaStream_t s0 = 0;

    // ---- fork ----
    cudaEventRecord(eRoot, s0);
    cudaStreamWaitEvent(s1, eRoot, 0);
    cudaStreamWaitEvent(s2, eRoot, 0);

    // s0: q,k,v -> fp16
    conv_h3<<<dim3((unsigned)(XEL / 1024), 1, 3), 256, 0, s0>>>(
        q, xq, k, xk, v, xv);
    cudaEventRecord(eC, s0);

    // s1: weight transposes -> Mt
    transpose_w3<<<dim3(16, 16, 24), dim3(32, 8), 0, s1>>>(
        Wq, wqt_h, wqt_l, Wk, wkt_h, wkt_l, Wv, wvt_h, wvt_l);
    cudaEventRecord(eT, s1);
    hmma_gemm<3, 1, false, 3, 0, false, false, 0>
        <<<dim3(4, 4, Hn), 256, SM3, s1>>>(
        wkt_h, wkt_l, wqt_h, wqt_l, nullptr, nullptr, mt, nullptr,
        Dn, Dn, Dn, Dn, WW, WW, 0, WW, 1.0f, 0);
    cudaEventRecord(eMt, s1);

    // s2: wvec, bfin, wo permute -> Wvo -> colv
    wvec_kernel<<<Hn, Dn, 0, s2>>>(Wk, bq, wvec);
    bfin_kernel<<<Dn, 256, 0, s2>>>(Wo, bv, bo, bfin);
    conv_wo_p<<<(unsigned)(WEL / 256), 256, 0, s2>>>(Wo, wop_h, wop_l);
    cudaStreamWaitEvent(s2, eT, 0);
    hmma_gemm<3, 1, false, 3, 0, false, false, 0>
        <<<dim3(4, 4, Hn), 256, SM3, s2>>>(
        wop_h, wop_l, wvt_h, wvt_l, nullptr, nullptr, wvo, nullptr,
        Dn, Dn, Hn * Dn, Dn, (size_t)Dn, WW, 0, WW, 1.0f, 0);
    cudaEventRecord(eWvo, s2);
    colv_kernel<<<Mn, 256, 0, s2>>>(k, wvec, colv, inv_scale);
    cudaEventRecord(e2end, s2);

    // s0: q~ = q @ Mt^T  (waits Mt)
    dim3 gproj(Dn / 128, Mn / 128, Hn);
    cudaStreamWaitEvent(s0, eMt, 0);
    hmma_gemm<1, 2, false, 3, 0, false, false, 0><<<gproj, 128, SM1B, s0>>>(
        xq, nullptr, mt, nullptr, nullptr, nullptr, qp, nullptr,
        Dn, Dn, Dn, Dn, 0, WW, 0, (size_t)Mn * Dn, 1.0f, 0);

    // s1: v~ = v @ Wvo^T  (waits Wvo + conv_h3)
    cudaStreamWaitEvent(s1, eWvo, 0);
    cudaStreamWaitEvent(s1, eC, 0);
    hmma_gemm<1, 2, false, 5, 0, false, false, 0><<<gproj, 128, SM1B, s1>>>(
        xv, nullptr, wvo, nullptr, nullptr, nullptr, vt2, nullptr,
        Dn, Dn, Dn, Dn, 0, WW, 0, 0, 1.0f, 0);
    cudaEventRecord(eV, s1);

    // s0: scores half 1 (b 0-7), waits colv
    cudaStreamWaitEvent(s0, e2end, 0);
    dim3 gsc(Nn / 128, Nn / 128, Hn * 8);
    hmma_gemm<1, 2, true, 6, 0, true, false, 1><<<gsc, 128, SM1B, s0>>>(
        qp, nullptr, xk, nullptr, colv, psum, Ps, nullptr,
        Nn, Dn, Dn, Dn, (size_t)Nn * Dn, (size_t)Nn * Dn,
        (size_t)Nn, (size_t)Nn * Nn, inv_scale, 0);
    cudaEventRecord(eS1, s0);
    inv_rsum_h8<<<256, 256, 0, s0>>>(psum, invr, 0);

    // s1: scores half 2 (b 8-15), starts after half 1 completes
    cudaStreamWaitEvent(s1, eS1, 0);
    hmma_gemm<1, 2, true, 6, 0, true, false, 1><<<gsc, 128, SM1B, s1>>>(
        qp, nullptr, xk, nullptr, colv, psum, Ps, nullptr,
        Nn, Dn, Dn, Dn, (size_t)Nn * Dn, (size_t)Nn * Dn,
        (size_t)Nn, (size_t)Nn * Nn, inv_scale, 8);
    inv_rsum_h8<<<256, 256, 0, s1>>>(psum, invr, 8);
    cudaEventRecord(eI2, s1);

    // s0: final half 1 (b 0-7), waits v~; co-runs with scores half 2
    cudaStreamWaitEvent(s0, eV, 0);
    dim3 gfin(Dn / 128, Nn / 128, 8);
    hmma_gemm<1, 2, true, 0, 2, false, true, 2><<<gfin, 128, SM1B, s0>>>(
        Ps, invr, vt2, nullptr, bfin, out, nullptr, nullptr,
        Dn, Hn * Nn, Nn, Hn * Nn,
        (size_t)Nn * Nn, (size_t)Dn * Hn * Nn, 0, (size_t)Nn * Dn, 1.0f, 0);

    // s0: final half 2 (b 8-15), waits scores half 2
    cudaStreamWaitEvent(s0, eI2, 0);
    hmma_gemm<1, 2, true, 0, 2, false, true, 2><<<gfin, 128, SM1B, s0>>>(
        Ps, invr, vt2, nullptr, bfin, out, nullptr, nullptr,
        Dn, Hn * Nn, Nn, Hn * Nn,
        (size_t)Nn * Nn, (size_t)Dn * Hn * Nn, 0, (size_t)Nn * Dn, 1.0f, 8);
}